// round 1
// baseline (speedup 1.0000x reference)
#include <cuda_runtime.h>

// ---------------------------------------------------------------------------
// Quantum multi-head attention, NQ=4, DIM=16, B=32, S=2048, L=1 layer.
// Stage 1: per-token 4-qubit circuit -> Q, K, V   (scratch in __device__ arrays)
// Stage 2: fused streaming attention (no-max softmax; scores bounded by |QK|/2<=2)
//          + final circuit (weights_C) in the epilogue -> d_out
// ---------------------------------------------------------------------------

#define B 32
#define S 2048
#define NTOK (B * S)     // 65536

__device__ float g_Q[NTOK * 4];
__device__ float g_K[NTOK * 4];
__device__ float g_V[NTOK * 4];

__device__ __forceinline__ float ex2_fast(float x) {
    float y;
    asm("ex2.approx.f32 %0, %1;" : "=f"(y) : "f"(x));
    return y;
}

// RX(theta) on the wire whose amplitude-index bit mask is M (wire q -> M = 1<<(3-q)).
// c = cos(theta/2), s = sin(theta/2).
// RX = [[c, -i s], [-i s, c]]:
//   new0 = c*a0 - i s*a1 ; new1 = c*a1 - i s*a0
template <int M>
__device__ __forceinline__ void rx_gate(float re[16], float im[16], float c, float s) {
#pragma unroll
    for (int i = 0; i < 16; ++i) {
        if (i & M) continue;
        const int j = i | M;
        float r0 = re[i], i0 = im[i], r1 = re[j], i1 = im[j];
        re[i] = c * r0 + s * i1;
        im[i] = c * i0 - s * r1;
        re[j] = c * r1 + s * i0;
        im[j] = c * i1 - s * r0;
    }
}

// Full circuit: RX(angles) on wires 0..3, RX(weights) on wires 0..3,
// CNOT ring (0,1)(1,2)(2,3)(3,0), then <Z_q> for q=0..3.
// ac/as = cos/sin of angle/2 per wire; wc/ws same for the layer weights.
__device__ __forceinline__ void run_circuit(const float ac[4], const float as_[4],
                                            const float wc[4], const float ws[4],
                                            float out[4]) {
    float re[16], im[16];
#pragma unroll
    for (int i = 0; i < 16; ++i) { re[i] = 0.0f; im[i] = 0.0f; }
    re[0] = 1.0f;

    // Angle embedding (wire q acts on bit 3-q).
    rx_gate<8>(re, im, ac[0], as_[0]);
    rx_gate<4>(re, im, ac[1], as_[1]);
    rx_gate<2>(re, im, ac[2], as_[2]);
    rx_gate<1>(re, im, ac[3], as_[3]);
    // Entangler layer RX.
    rx_gate<8>(re, im, wc[0], ws[0]);
    rx_gate<4>(re, im, wc[1], ws[1]);
    rx_gate<2>(re, im, wc[2], ws[2]);
    rx_gate<1>(re, im, wc[3], ws[3]);

    // CNOT ring as register swaps (perm[i] = i ^ mt when control bit set; CNOT == its own inverse).
#define SWAP_AMP(a, b) { float t = re[a]; re[a] = re[b]; re[b] = t; \
                         t = im[a]; im[a] = im[b]; im[b] = t; }
    // CNOT(0,1): mc=8, mt=4
    SWAP_AMP(8, 12)  SWAP_AMP(9, 13)  SWAP_AMP(10, 14) SWAP_AMP(11, 15)
    // CNOT(1,2): mc=4, mt=2
    SWAP_AMP(4, 6)   SWAP_AMP(5, 7)   SWAP_AMP(12, 14) SWAP_AMP(13, 15)
    // CNOT(2,3): mc=2, mt=1
    SWAP_AMP(2, 3)   SWAP_AMP(6, 7)   SWAP_AMP(10, 11) SWAP_AMP(14, 15)
    // CNOT(3,0): mc=1, mt=8
    SWAP_AMP(1, 9)   SWAP_AMP(3, 11)  SWAP_AMP(5, 13)  SWAP_AMP(7, 15)
#undef SWAP_AMP

    float p[16];
#pragma unroll
    for (int i = 0; i < 16; ++i) p[i] = re[i] * re[i] + im[i] * im[i];

    float o0 = 0.f, o1 = 0.f, o2 = 0.f, o3 = 0.f;
#pragma unroll
    for (int i = 0; i < 16; ++i) {
        o0 += (i & 8) ? -p[i] : p[i];
        o1 += (i & 4) ? -p[i] : p[i];
        o2 += (i & 2) ? -p[i] : p[i];
        o3 += (i & 1) ? -p[i] : p[i];
    }
    out[0] = o0; out[1] = o1; out[2] = o2; out[3] = o3;
}

// ---------------------------------------------------------------------------
// Kernel 1: token circuits -> Q, K, V
// ---------------------------------------------------------------------------
__global__ void __launch_bounds__(256) qkv_kernel(const float4* __restrict__ x,
                                                  const float* __restrict__ wQ,
                                                  const float* __restrict__ wK,
                                                  const float* __restrict__ wV) {
    int t = blockIdx.x * 256 + threadIdx.x;   // grid sized exactly NTOK
    float4 a = x[t];
    float ac[4], as_[4];
    __sincosf(0.5f * a.x, &as_[0], &ac[0]);
    __sincosf(0.5f * a.y, &as_[1], &ac[1]);
    __sincosf(0.5f * a.z, &as_[2], &ac[2]);
    __sincosf(0.5f * a.w, &as_[3], &ac[3]);

    float wc[4], ws[4], o[4];

#pragma unroll
    for (int q = 0; q < 4; ++q) __sincosf(0.5f * __ldg(&wQ[q]), &ws[q], &wc[q]);
    run_circuit(ac, as_, wc, ws, o);
    reinterpret_cast<float4*>(g_Q)[t] = make_float4(o[0], o[1], o[2], o[3]);

#pragma unroll
    for (int q = 0; q < 4; ++q) __sincosf(0.5f * __ldg(&wK[q]), &ws[q], &wc[q]);
    run_circuit(ac, as_, wc, ws, o);
    reinterpret_cast<float4*>(g_K)[t] = make_float4(o[0], o[1], o[2], o[3]);

#pragma unroll
    for (int q = 0; q < 4; ++q) __sincosf(0.5f * __ldg(&wV[q]), &ws[q], &wc[q]);
    run_circuit(ac, as_, wc, ws, o);
    reinterpret_cast<float4*>(g_V)[t] = make_float4(o[0], o[1], o[2], o[3]);
}

// ---------------------------------------------------------------------------
// Kernel 2: fused attention + final circuit.
// Grid (B, S/128), 128 threads; each thread owns one query row.
// K/V streamed through smem in 4 chunks of 512 keys (16 KB static smem).
// Softmax without max-subtraction: scores = (Q.K)/2 with |Q_i|,|K_i| <= 1
// => |score| <= 2, exp is safe. Fold 0.5*log2(e) into Q so exp == one EX2.
// ---------------------------------------------------------------------------
#define CHUNK 512

__global__ void __launch_bounds__(128) attn_kernel(const float* __restrict__ wC,
                                                   float4* __restrict__ out) {
    __shared__ float4 sk[CHUNK];
    __shared__ float4 sv[CHUNK];

    const int b = blockIdx.x;
    const int r = blockIdx.y * 128 + threadIdx.x;

    const float4* __restrict__ Kb = reinterpret_cast<const float4*>(g_K) + b * S;
    const float4* __restrict__ Vb = reinterpret_cast<const float4*>(g_V) + b * S;

    float4 q = reinterpret_cast<const float4*>(g_Q)[b * S + r];
    const float SC = 0.5f * 1.4426950408889634f;   // (1/sqrt(E)) * log2(e)
    q.x *= SC; q.y *= SC; q.z *= SC; q.w *= SC;

    float ssum = 0.f, a0 = 0.f, a1 = 0.f, a2 = 0.f, a3 = 0.f;

    for (int chunk = 0; chunk < S / CHUNK; ++chunk) {
        __syncthreads();   // protect smem from previous chunk's readers
#pragma unroll
        for (int i = 0; i < CHUNK / 128; ++i) {
            int idx = i * 128 + threadIdx.x;
            sk[idx] = Kb[chunk * CHUNK + idx];
            sv[idx] = Vb[chunk * CHUNK + idx];
        }
        __syncthreads();

#pragma unroll 8
        for (int k = 0; k < CHUNK; ++k) {
            float4 kk = sk[k];          // broadcast LDS.128
            float4 vv = sv[k];
            float d = q.x * kk.x + q.y * kk.y + q.z * kk.z + q.w * kk.w;
            float e = ex2_fast(d);
            ssum += e;
            a0 += e * vv.x;
            a1 += e * vv.y;
            a2 += e * vv.z;
            a3 += e * vv.w;
        }
    }

    float inv = 1.0f / ssum;
    float ctx0 = a0 * inv, ctx1 = a1 * inv, ctx2 = a2 * inv, ctx3 = a3 * inv;

    // Final circuit on ctx with weights_C.
    float cc[4], cs[4], wc[4], ws[4], o[4];
    __sincosf(0.5f * ctx0, &cs[0], &cc[0]);
    __sincosf(0.5f * ctx1, &cs[1], &cc[1]);
    __sincosf(0.5f * ctx2, &cs[2], &cc[2]);
    __sincosf(0.5f * ctx3, &cs[3], &cc[3]);
#pragma unroll
    for (int i = 0; i < 4; ++i) __sincosf(0.5f * __ldg(&wC[i]), &ws[i], &wc[i]);
    run_circuit(cc, cs, wc, ws, o);

    out[b * S + r] = make_float4(o[0], o[1], o[2], o[3]);
}

// ---------------------------------------------------------------------------
extern "C" void kernel_launch(void* const* d_in, const int* in_sizes, int n_in,
                              void* d_out, int out_size) {
    (void)in_sizes; (void)n_in; (void)out_size;
    const float4* x  = (const float4*)d_in[0];
    const float*  wQ = (const float*)d_in[1];
    const float*  wK = (const float*)d_in[2];
    const float*  wV = (const float*)d_in[3];
    const float*  wC = (const float*)d_in[4];

    qkv_kernel<<<NTOK / 256, 256>>>(x, wQ, wK, wV);
    attn_kernel<<<dim3(B, S / 128), 128>>>(wC, (float4*)d_out);
}

// round 2
// speedup vs baseline: 1.1872x; 1.1872x over previous
#include <cuda_runtime.h>

// ---------------------------------------------------------------------------
// Quantum multi-head attention, NQ=4, DIM=16, B=32, S=2048.
// K1: per-token circuits -> Q,K,V.
// K2: attention mainloop, packed f32x2 math, 2 queries/thread, key dim split
//     4 ways into additive softmax partials (scores bounded, no max needed).
// K3: combine partials, normalize, final circuit -> out.
// ---------------------------------------------------------------------------

#define B 32
#define S 2048
#define NTOK (B * S)     // 65536
#define KSPLIT 4
#define KCHUNK (S / KSPLIT)   // 512 keys per block
#define QTILE 256             // queries per block (128 threads x 2)

__device__ float g_Q[NTOK * 4];
__device__ float g_K[NTOK * 4];
__device__ float g_V[NTOK * 4];
__device__ float4 g_p0[NTOK * KSPLIT];   // (ssum, a0, a1, a2)
__device__ float  g_p1[NTOK * KSPLIT];   // a3

typedef unsigned long long u64;

__device__ __forceinline__ float ex2_fast(float x) {
    float y;
    asm("ex2.approx.f32 %0, %1;" : "=f"(y) : "f"(x));
    return y;
}
__device__ __forceinline__ u64 mul2(u64 a, u64 b) {
    u64 d; asm("mul.rn.f32x2 %0,%1,%2;" : "=l"(d) : "l"(a), "l"(b)); return d;
}
__device__ __forceinline__ u64 fma2(u64 a, u64 b, u64 c) {
    u64 d; asm("fma.rn.f32x2 %0,%1,%2,%3;" : "=l"(d) : "l"(a), "l"(b), "l"(c)); return d;
}
__device__ __forceinline__ float2 u2f(u64 u) {
    float2 f; asm("mov.b64 {%0,%1}, %2;" : "=f"(f.x), "=f"(f.y) : "l"(u)); return f;
}
__device__ __forceinline__ u64 f2u(float a, float b) {
    u64 u; asm("mov.b64 %0, {%1,%2};" : "=l"(u) : "f"(a), "f"(b)); return u;
}

// RX on amplitude-bit mask M (wire q -> M = 1<<(3-q)).
template <int M>
__device__ __forceinline__ void rx_gate(float re[16], float im[16], float c, float s) {
#pragma unroll
    for (int i = 0; i < 16; ++i) {
        if (i & M) continue;
        const int j = i | M;
        float r0 = re[i], i0 = im[i], r1 = re[j], i1 = im[j];
        re[i] = c * r0 + s * i1;
        im[i] = c * i0 - s * r1;
        re[j] = c * r1 + s * i0;
        im[j] = c * i1 - s * r0;
    }
}

__device__ __forceinline__ void run_circuit(const float ac[4], const float as_[4],
                                            const float wc[4], const float ws[4],
                                            float out[4]) {
    float re[16], im[16];
#pragma unroll
    for (int i = 0; i < 16; ++i) { re[i] = 0.0f; im[i] = 0.0f; }
    re[0] = 1.0f;

    rx_gate<8>(re, im, ac[0], as_[0]);
    rx_gate<4>(re, im, ac[1], as_[1]);
    rx_gate<2>(re, im, ac[2], as_[2]);
    rx_gate<1>(re, im, ac[3], as_[3]);
    rx_gate<8>(re, im, wc[0], ws[0]);
    rx_gate<4>(re, im, wc[1], ws[1]);
    rx_gate<2>(re, im, wc[2], ws[2]);
    rx_gate<1>(re, im, wc[3], ws[3]);

#define SWAP_AMP(a, b) { float t = re[a]; re[a] = re[b]; re[b] = t; \
                         t = im[a]; im[a] = im[b]; im[b] = t; }
    SWAP_AMP(8, 12)  SWAP_AMP(9, 13)  SWAP_AMP(10, 14) SWAP_AMP(11, 15)   // CNOT(0,1)
    SWAP_AMP(4, 6)   SWAP_AMP(5, 7)   SWAP_AMP(12, 14) SWAP_AMP(13, 15)   // CNOT(1,2)
    SWAP_AMP(2, 3)   SWAP_AMP(6, 7)   SWAP_AMP(10, 11) SWAP_AMP(14, 15)   // CNOT(2,3)
    SWAP_AMP(1, 9)   SWAP_AMP(3, 11)  SWAP_AMP(5, 13)  SWAP_AMP(7, 15)    // CNOT(3,0)
#undef SWAP_AMP

    float p[16];
#pragma unroll
    for (int i = 0; i < 16; ++i) p[i] = re[i] * re[i] + im[i] * im[i];

    float o0 = 0.f, o1 = 0.f, o2 = 0.f, o3 = 0.f;
#pragma unroll
    for (int i = 0; i < 16; ++i) {
        o0 += (i & 8) ? -p[i] : p[i];
        o1 += (i & 4) ? -p[i] : p[i];
        o2 += (i & 2) ? -p[i] : p[i];
        o3 += (i & 1) ? -p[i] : p[i];
    }
    out[0] = o0; out[1] = o1; out[2] = o2; out[3] = o3;
}

// ---------------------------------------------------------------------------
// K1: token circuits -> Q, K, V
// ---------------------------------------------------------------------------
__global__ void __launch_bounds__(256) qkv_kernel(const float4* __restrict__ x,
                                                  const float* __restrict__ wQ,
                                                  const float* __restrict__ wK,
                                                  const float* __restrict__ wV) {
    int t = blockIdx.x * 256 + threadIdx.x;
    float4 a = x[t];
    float ac[4], as_[4];
    __sincosf(0.5f * a.x, &as_[0], &ac[0]);
    __sincosf(0.5f * a.y, &as_[1], &ac[1]);
    __sincosf(0.5f * a.z, &as_[2], &ac[2]);
    __sincosf(0.5f * a.w, &as_[3], &ac[3]);

    float wc[4], ws[4], o[4];

#pragma unroll
    for (int q = 0; q < 4; ++q) __sincosf(0.5f * __ldg(&wQ[q]), &ws[q], &wc[q]);
    run_circuit(ac, as_, wc, ws, o);
    reinterpret_cast<float4*>(g_Q)[t] = make_float4(o[0], o[1], o[2], o[3]);

#pragma unroll
    for (int q = 0; q < 4; ++q) __sincosf(0.5f * __ldg(&wK[q]), &ws[q], &wc[q]);
    run_circuit(ac, as_, wc, ws, o);
    reinterpret_cast<float4*>(g_K)[t] = make_float4(o[0], o[1], o[2], o[3]);

#pragma unroll
    for (int q = 0; q < 4; ++q) __sincosf(0.5f * __ldg(&wV[q]), &ws[q], &wc[q]);
    run_circuit(ac, as_, wc, ws, o);
    reinterpret_cast<float4*>(g_V)[t] = make_float4(o[0], o[1], o[2], o[3]);
}

// ---------------------------------------------------------------------------
// K2: attention partials.
// grid (B, S/QTILE, KSPLIT), 128 threads. Thread owns queries (qb+t, qb+t+128),
// processes KCHUNK keys held in smem. Packed f32x2 throughout.
// exp2 folding: scores=(Q.K)/2, |score|<=2 -> no max subtraction needed.
// ---------------------------------------------------------------------------
__global__ void __launch_bounds__(128) attn_kernel() {
    __shared__ ulonglong2 sk[KCHUNK];
    __shared__ ulonglong2 sv[KCHUNK];

    const int b  = blockIdx.x;
    const int qb = blockIdx.y * QTILE;
    const int kq = blockIdx.z;
    const int t  = threadIdx.x;

    const ulonglong2* __restrict__ Kb =
        reinterpret_cast<const ulonglong2*>(g_K) + b * S + kq * KCHUNK;
    const ulonglong2* __restrict__ Vb =
        reinterpret_cast<const ulonglong2*>(g_V) + b * S + kq * KCHUNK;

#pragma unroll
    for (int i = 0; i < KCHUNK / 128; ++i) {
        sk[i * 128 + t] = Kb[i * 128 + t];
        sv[i * 128 + t] = Vb[i * 128 + t];
    }

    // Load 2 queries, fold in (1/sqrt(E)) * log2(e) scale.
    const float SC = 0.5f * 1.4426950408889634f;
    float4 qa = reinterpret_cast<const float4*>(g_Q)[b * S + qb + t];
    float4 qc = reinterpret_cast<const float4*>(g_Q)[b * S + qb + t + 128];
    u64 q0lo = f2u(qa.x * SC, qa.y * SC), q0hi = f2u(qa.z * SC, qa.w * SC);
    u64 q1lo = f2u(qc.x * SC, qc.y * SC), q1hi = f2u(qc.z * SC, qc.w * SC);

    u64 acc00 = f2u(0.f, 0.f), acc01 = acc00, acc10 = acc00, acc11 = acc00;
    float s0 = 0.f, s1 = 0.f;

    __syncthreads();

#pragma unroll 4
    for (int k = 0; k < KCHUNK; ++k) {
        ulonglong2 kk = sk[k];          // LDS.128 broadcast
        ulonglong2 vv = sv[k];

        // query 0
        u64 d0 = fma2(q0hi, kk.y, mul2(q0lo, kk.x));
        float2 d0f = u2f(d0);
        float e0 = ex2_fast(d0f.x + d0f.y);
        u64 ee0 = f2u(e0, e0);
        acc00 = fma2(ee0, vv.x, acc00);
        acc01 = fma2(ee0, vv.y, acc01);
        s0 += e0;

        // query 1
        u64 d1 = fma2(q1hi, kk.y, mul2(q1lo, kk.x));
        float2 d1f = u2f(d1);
        float e1 = ex2_fast(d1f.x + d1f.y);
        u64 ee1 = f2u(e1, e1);
        acc10 = fma2(ee1, vv.x, acc10);
        acc11 = fma2(ee1, vv.y, acc11);
        s1 += e1;
    }

    const int base = ((b * KSPLIT + kq) << 11) + qb + t;   // ((b*4+kq)*2048 + q)
    float2 a00 = u2f(acc00), a01 = u2f(acc01);
    g_p0[base] = make_float4(s0, a00.x, a00.y, a01.x);
    g_p1[base] = a01.y;
    float2 a10 = u2f(acc10), a11 = u2f(acc11);
    g_p0[base + 128] = make_float4(s1, a10.x, a10.y, a11.x);
    g_p1[base + 128] = a11.y;
}

// ---------------------------------------------------------------------------
// K3: combine KSPLIT partials, normalize, final circuit -> out.
// ---------------------------------------------------------------------------
__global__ void __launch_bounds__(256) reduce_kernel(const float* __restrict__ wC,
                                                     float4* __restrict__ out) {
    int g = blockIdx.x * 256 + threadIdx.x;  // global query 0..NTOK-1
    int b = g >> 11;
    int q = g & (S - 1);

    float ssum = 0.f, a0 = 0.f, a1 = 0.f, a2 = 0.f, a3 = 0.f;
#pragma unroll
    for (int kq = 0; kq < KSPLIT; ++kq) {
        int idx = ((b * KSPLIT + kq) << 11) + q;
        float4 p = g_p0[idx];
        ssum += p.x; a0 += p.y; a1 += p.z; a2 += p.w;
        a3 += g_p1[idx];
    }
    float inv = 1.0f / ssum;

    float cc[4], cs[4], wc[4], ws[4], o[4];
    __sincosf(0.5f * a0 * inv, &cs[0], &cc[0]);
    __sincosf(0.5f * a1 * inv, &cs[1], &cc[1]);
    __sincosf(0.5f * a2 * inv, &cs[2], &cc[2]);
    __sincosf(0.5f * a3 * inv, &cs[3], &cc[3]);
#pragma unroll
    for (int i = 0; i < 4; ++i) __sincosf(0.5f * __ldg(&wC[i]), &ws[i], &wc[i]);
    run_circuit(cc, cs, wc, ws, o);

    out[g] = make_float4(o[0], o[1], o[2], o[3]);
}

// ---------------------------------------------------------------------------
extern "C" void kernel_launch(void* const* d_in, const int* in_sizes, int n_in,
                              void* d_out, int out_size) {
    (void)in_sizes; (void)n_in; (void)out_size;
    const float4* x  = (const float4*)d_in[0];
    const float*  wQ = (const float*)d_in[1];
    const float*  wK = (const float*)d_in[2];
    const float*  wV = (const float*)d_in[3];
    const float*  wC = (const float*)d_in[4];

    qkv_kernel<<<NTOK / 256, 256>>>(x, wQ, wK, wV);
    attn_kernel<<<dim3(B, S / QTILE, KSPLIT), 128>>>();
    reduce_kernel<<<NTOK / 256, 256>>>(wC, (float4*)d_out);
}

// round 4
// speedup vs baseline: 1.3254x; 1.1164x over previous
#include <cuda_runtime.h>

// ---------------------------------------------------------------------------
// Quantum multi-head attention, NQ=4, DIM=16, B=32, S=2048.
// K1: per-token circuits -> Q(pre-scaled by log2e/2), K, V. 3x parallel over QKV.
// K2: attention partials: 4 queries/thread, KSPLIT=8, packed f32x2 math,
//     no-max softmax (|score| bounded by 2).
// K3: combine 8 partials, normalize, final circuit -> out.
// ---------------------------------------------------------------------------

#define B 32
#define S 2048
#define NTOK (B * S)          // 65536
#define KSPLIT 8
#define KCHUNK (S / KSPLIT)   // 256 keys per block
#define QPT 4                 // queries per thread
#define QTILE (128 * QPT)     // 512 queries per block

__device__ float g_Q[NTOK * 4];
__device__ float g_K[NTOK * 4];
__device__ float g_V[NTOK * 4];
__device__ float4 g_p0[NTOK * KSPLIT];   // (ssum, a0, a1, a2)
__device__ float  g_p1[NTOK * KSPLIT];   // a3

typedef unsigned long long u64;

__device__ __forceinline__ float ex2_fast(float x) {
    float y;
    asm("ex2.approx.f32 %0, %1;" : "=f"(y) : "f"(x));
    return y;
}
__device__ __forceinline__ u64 mul2(u64 a, u64 b) {
    u64 d; asm("mul.rn.f32x2 %0,%1,%2;" : "=l"(d) : "l"(a), "l"(b)); return d;
}
__device__ __forceinline__ u64 fma2(u64 a, u64 b, u64 c) {
    u64 d; asm("fma.rn.f32x2 %0,%1,%2,%3;" : "=l"(d) : "l"(a), "l"(b), "l"(c)); return d;
}
__device__ __forceinline__ float2 u2f(u64 u) {
    float2 f; asm("mov.b64 {%0,%1}, %2;" : "=f"(f.x), "=f"(f.y) : "l"(u)); return f;
}
__device__ __forceinline__ u64 f2u(float a, float b) {
    u64 u; asm("mov.b64 %0, {%1,%2};" : "=l"(u) : "f"(a), "f"(b)); return u;
}

// RX on amplitude-bit mask M (wire q -> M = 1<<(3-q)).
template <int M>
__device__ __forceinline__ void rx_gate(float re[16], float im[16], float c, float s) {
#pragma unroll
    for (int i = 0; i < 16; ++i) {
        if (i & M) continue;
        const int j = i | M;
        float r0 = re[i], i0 = im[i], r1 = re[j], i1 = im[j];
        re[i] = c * r0 + s * i1;
        im[i] = c * i0 - s * r1;
        re[j] = c * r1 + s * i0;
        im[j] = c * i1 - s * r0;
    }
}

__device__ __forceinline__ void run_circuit(const float ac[4], const float as_[4],
                                            const float wc[4], const float ws[4],
                                            float out[4]) {
    float re[16], im[16];
#pragma unroll
    for (int i = 0; i < 16; ++i) { re[i] = 0.0f; im[i] = 0.0f; }
    re[0] = 1.0f;

    rx_gate<8>(re, im, ac[0], as_[0]);
    rx_gate<4>(re, im, ac[1], as_[1]);
    rx_gate<2>(re, im, ac[2], as_[2]);
    rx_gate<1>(re, im, ac[3], as_[3]);
    rx_gate<8>(re, im, wc[0], ws[0]);
    rx_gate<4>(re, im, wc[1], ws[1]);
    rx_gate<2>(re, im, wc[2], ws[2]);
    rx_gate<1>(re, im, wc[3], ws[3]);

#define SWAP_AMP(a, b) { float t = re[a]; re[a] = re[b]; re[b] = t; \
                         t = im[a]; im[a] = im[b]; im[b] = t; }
    SWAP_AMP(8, 12)  SWAP_AMP(9, 13)  SWAP_AMP(10, 14) SWAP_AMP(11, 15)   // CNOT(0,1)
    SWAP_AMP(4, 6)   SWAP_AMP(5, 7)   SWAP_AMP(12, 14) SWAP_AMP(13, 15)   // CNOT(1,2)
    SWAP_AMP(2, 3)   SWAP_AMP(6, 7)   SWAP_AMP(10, 11) SWAP_AMP(14, 15)   // CNOT(2,3)
    SWAP_AMP(1, 9)   SWAP_AMP(3, 11)  SWAP_AMP(5, 13)  SWAP_AMP(7, 15)    // CNOT(3,0)
#undef SWAP_AMP

    float p[16];
#pragma unroll
    for (int i = 0; i < 16; ++i) p[i] = re[i] * re[i] + im[i] * im[i];

    float o0 = 0.f, o1 = 0.f, o2 = 0.f, o3 = 0.f;
#pragma unroll
    for (int i = 0; i < 16; ++i) {
        o0 += (i & 8) ? -p[i] : p[i];
        o1 += (i & 4) ? -p[i] : p[i];
        o2 += (i & 2) ? -p[i] : p[i];
        o3 += (i & 1) ? -p[i] : p[i];
    }
    out[0] = o0; out[1] = o1; out[2] = o2; out[3] = o3;
}

// ---------------------------------------------------------------------------
// K1: token circuits. blockIdx.y selects which of {Q,K,V} this block computes.
// Q is pre-scaled by (1/sqrt(E)) * log2(e) = 0.5*log2(e).
// ---------------------------------------------------------------------------
__global__ void __launch_bounds__(128) qkv_kernel(const float4* __restrict__ x,
                                                  const float* __restrict__ wQ,
                                                  const float* __restrict__ wK,
                                                  const float* __restrict__ wV) {
    const int t = blockIdx.x * 128 + threadIdx.x;
    const int which = blockIdx.y;

    float4 a = x[t];
    float ac[4], as_[4];
    __sincosf(0.5f * a.x, &as_[0], &ac[0]);
    __sincosf(0.5f * a.y, &as_[1], &ac[1]);
    __sincosf(0.5f * a.z, &as_[2], &ac[2]);
    __sincosf(0.5f * a.w, &as_[3], &ac[3]);

    const float* w = (which == 0) ? wQ : (which == 1) ? wK : wV;
    float* dst     = (which == 0) ? g_Q : (which == 1) ? g_K : g_V;
    const float scale = (which == 0) ? (0.5f * 1.4426950408889634f) : 1.0f;

    float wc[4], ws[4], o[4];
#pragma unroll
    for (int q = 0; q < 4; ++q) __sincosf(0.5f * __ldg(&w[q]), &ws[q], &wc[q]);
    run_circuit(ac, as_, wc, ws, o);
    reinterpret_cast<float4*>(dst)[t] =
        make_float4(o[0] * scale, o[1] * scale, o[2] * scale, o[3] * scale);
}

// ---------------------------------------------------------------------------
// K2: attention partials. grid (B, S/QTILE, KSPLIT), 128 threads.
// Thread owns queries qb + t + {0,128,256,384}; KCHUNK keys via smem.
// ---------------------------------------------------------------------------
__global__ void __launch_bounds__(128) attn_kernel() {
    __shared__ ulonglong2 sk[KCHUNK];
    __shared__ ulonglong2 sv[KCHUNK];

    const int b  = blockIdx.x;
    const int qb = blockIdx.y * QTILE;
    const int kq = blockIdx.z;
    const int t  = threadIdx.x;

    const ulonglong2* __restrict__ Kb =
        reinterpret_cast<const ulonglong2*>(g_K) + b * S + kq * KCHUNK;
    const ulonglong2* __restrict__ Vb =
        reinterpret_cast<const ulonglong2*>(g_V) + b * S + kq * KCHUNK;

#pragma unroll
    for (int i = 0; i < KCHUNK / 128; ++i) {
        sk[i * 128 + t] = Kb[i * 128 + t];
        sv[i * 128 + t] = Vb[i * 128 + t];
    }

    u64 qlo[QPT], qhi[QPT];
    u64 acc0[QPT], acc1[QPT];
    float ss[QPT];
#pragma unroll
    for (int j = 0; j < QPT; ++j) {
        float4 qv = reinterpret_cast<const float4*>(g_Q)[b * S + qb + t + j * 128];
        qlo[j] = f2u(qv.x, qv.y);
        qhi[j] = f2u(qv.z, qv.w);
        acc0[j] = f2u(0.f, 0.f);
        acc1[j] = f2u(0.f, 0.f);
        ss[j] = 0.f;
    }

    __syncthreads();

#pragma unroll 2
    for (int k = 0; k < KCHUNK; ++k) {
        ulonglong2 kk = sk[k];      // LDS.128 broadcast
        ulonglong2 vv = sv[k];
#pragma unroll
        for (int j = 0; j < QPT; ++j) {
            u64 d = fma2(qhi[j], kk.y, mul2(qlo[j], kk.x));
            float2 df = u2f(d);
            float e = ex2_fast(df.x + df.y);
            u64 ee = f2u(e, e);
            acc0[j] = fma2(ee, vv.x, acc0[j]);
            acc1[j] = fma2(ee, vv.y, acc1[j]);
            ss[j] += e;
        }
    }

    const int base = ((b * KSPLIT + kq) << 11) + qb + t;   // ((b*KSPLIT+kq)*S + q)
#pragma unroll
    for (int j = 0; j < QPT; ++j) {
        float2 a0 = u2f(acc0[j]), a1 = u2f(acc1[j]);
        g_p0[base + j * 128] = make_float4(ss[j], a0.x, a0.y, a1.x);
        g_p1[base + j * 128] = a1.y;
    }
}

// ---------------------------------------------------------------------------
// K3: combine KSPLIT partials, normalize, final circuit -> out.
// ---------------------------------------------------------------------------
__global__ void __launch_bounds__(128) reduce_kernel(const float* __restrict__ wC,
                                                     float4* __restrict__ out) {
    int g = blockIdx.x * 128 + threadIdx.x;  // global query 0..NTOK-1
    int b = g >> 11;
    int q = g & (S - 1);

    float ssum = 0.f, a0 = 0.f, a1 = 0.f, a2 = 0.f, a3 = 0.f;
#pragma unroll
    for (int kq = 0; kq < KSPLIT; ++kq) {
        int idx = ((b * KSPLIT + kq) << 11) + q;
        float4 p = g_p0[idx];
        ssum += p.x; a0 += p.y; a1 += p.z; a2 += p.w;
        a3 += g_p1[idx];
    }
    float inv = 1.0f / ssum;

    float cc[4], cs[4], wc[4], ws[4], o[4];
    __sincosf(0.5f * a0 * inv, &cs[0], &cc[0]);
    __sincosf(0.5f * a1 * inv, &cs[1], &cc[1]);
    __sincosf(0.5f * a2 * inv, &cs[2], &cc[2]);
    __sincosf(0.5f * a3 * inv, &cs[3], &cc[3]);
#pragma unroll
    for (int i = 0; i < 4; ++i) __sincosf(0.5f * __ldg(&wC[i]), &ws[i], &wc[i]);
    run_circuit(cc, cs, wc, ws, o);

    out[g] = make_float4(o[0], o[1], o[2], o[3]);
}

// ---------------------------------------------------------------------------
extern "C" void kernel_launch(void* const* d_in, const int* in_sizes, int n_in,
                              void* d_out, int out_size) {
    (void)in_sizes; (void)n_in; (void)out_size;
    const float4* x  = (const float4*)d_in[0];
    const float*  wQ = (const float*)d_in[1];
    const float*  wK = (const float*)d_in[2];
    const float*  wV = (const float*)d_in[3];
    const float*  wC = (const float*)d_in[4];

    qkv_kernel<<<dim3(NTOK / 128, 3), 128>>>(x, wQ, wK, wV);
    attn_kernel<<<dim3(B, S / QTILE, KSPLIT), 128>>>();
    reduce_kernel<<<NTOK / 128, 128>>>(wC, (float4*)d_out);
}